// round 3
// baseline (speedup 1.0000x reference)
#include <cuda_runtime.h>
#include <math.h>

// ---------------- problem constants ----------------
#define BATCH   16
#define LSEQ    1024
#define DMODEL  64
#define DINNER  128
#define SSTATE  16
#define MROWS   (BATCH*LSEQ)   // 16384
#define HFFN    256
#define NNODE   1024
#define EDIM    10
#define PLOUT   96

// ---------------- scratch (single static device buffer) ----------------
__device__ float g_scratch[47263744];

__device__ __forceinline__ float silu_(float x) { return x / (1.f + __expf(-x)); }

// ---------------- prep: fold weights, A = -exp(Alog), copy x ----------------
__global__ void prep_k(const float* __restrict__ fw_in, const float* __restrict__ bw_in,
                       const float* __restrict__ fwx, const float* __restrict__ fwdt,
                       const float* __restrict__ bwx, const float* __restrict__ bwdt,
                       const float* __restrict__ fwA, const float* __restrict__ bwA,
                       const float* __restrict__ x_in,
                       float* __restrict__ Wcat, float* __restrict__ Wcomb0,
                       float* __restrict__ Wcomb1, float* __restrict__ A0,
                       float* __restrict__ A1, float* __restrict__ xbuf)
{
    int g = blockIdx.x * 256 + threadIdx.x;
    if (g < 32768) {  // Wcat (64,512)
        int k = g >> 9, j = g & 511;
        Wcat[g] = (j < 256) ? fw_in[k*256 + j] : bw_in[k*256 + (j-256)];
        return;
    }
    int h = g - 32768;
    if (h < 40960) {  // Wcomb (2 x 128 x 160)
        int dir = h / 20480; int r2 = h % 20480;
        int i = r2 / 160, j = r2 % 160;
        const float* Wx  = dir ? bwx  : fwx;
        const float* Wdt = dir ? bwdt : fwdt;
        float v;
        if (j < 128) {
            v = 0.f;
            #pragma unroll
            for (int r = 0; r < 4; r++) v = fmaf(Wx[i*36 + r], Wdt[r*128 + j], v);
        } else {
            v = Wx[i*36 + 4 + (j - 128)];
        }
        (dir ? Wcomb1 : Wcomb0)[i*160 + j] = v;
        return;
    }
    h -= 40960;
    if (h < 4096) {  // A
        int dir = h >> 11; int i = h & 2047;
        (dir ? A1 : A0)[i] = -__expf((dir ? bwA : fwA)[i]);
        return;
    }
    h -= 4096;
    if (h < MROWS*DMODEL) xbuf[h] = x_in[h];
}

// ---------------- generic tiled SGEMM with epilogues ----------------
// EPI: 0 store, 1 xproj-split(softplus dt | Bm | Cm), 2 bias+relu, 3 +aux0(full),
//      4 +aux0(full)+aux1(col), 5 2v - I, 6 +aux0(col)
template<int EPI>
__global__ void __launch_bounds__(256) sgemm_k(
    const float* __restrict__ A, const float* __restrict__ B, float* __restrict__ C,
    int M, int N, int K, long long sA, long long sB, long long sC,
    const float* __restrict__ aux0, const float* __restrict__ aux1,
    float* __restrict__ o1, float* __restrict__ o2)
{
    __shared__ float As[16][64];
    __shared__ float Bs[16][64];
    int bz = blockIdx.z;
    A += sA * bz; B += sB * bz; C += sC * bz;
    int row0 = blockIdx.y * 64, col0 = blockIdx.x * 64;
    int tid = threadIdx.x;
    int tx = tid & 15, ty = tid >> 4;
    int a_m = tid >> 2, a_k = (tid & 3) * 4;
    int b_k = tid >> 4, b_n = (tid & 15) * 4;
    float acc[4][4];
    #pragma unroll
    for (int i = 0; i < 4; i++)
        #pragma unroll
        for (int j = 0; j < 4; j++) acc[i][j] = 0.f;

    for (int k0 = 0; k0 < K; k0 += 16) {
        float4 av = *(const float4*)(A + (size_t)(row0 + a_m)*K + k0 + a_k);
        As[a_k+0][a_m] = av.x; As[a_k+1][a_m] = av.y;
        As[a_k+2][a_m] = av.z; As[a_k+3][a_m] = av.w;
        int bc = col0 + b_n;
        float4 bv = make_float4(0.f, 0.f, 0.f, 0.f);
        if (bc < N) bv = *(const float4*)(B + (size_t)(k0 + b_k)*N + bc);
        *(float4*)&Bs[b_k][b_n] = bv;
        __syncthreads();
        #pragma unroll
        for (int kk = 0; kk < 16; kk++) {
            float am[4], bn[4];
            *(float4*)am = *(const float4*)&As[kk][ty*4];
            *(float4*)bn = *(const float4*)&Bs[kk][tx*4];
            #pragma unroll
            for (int i = 0; i < 4; i++)
                #pragma unroll
                for (int j = 0; j < 4; j++)
                    acc[i][j] = fmaf(am[i], bn[j], acc[i][j]);
        }
        __syncthreads();
    }

    #pragma unroll
    for (int i = 0; i < 4; i++) {
        int row = row0 + ty*4 + i;
        #pragma unroll
        for (int j = 0; j < 4; j++) {
            int col = col0 + tx*4 + j;
            if (col >= N) continue;
            float v = acc[i][j];
            size_t idx = (size_t)row * N + col;
            if (EPI == 0) {
                C[idx] = v;
            } else if (EPI == 1) {
                if (col < 128) {
                    float t = v + aux0[col];
                    C[(size_t)row*128 + col] = (t > 20.f) ? t : log1pf(__expf(t));
                } else if (col < 144) {
                    o1[(size_t)row*16 + (col - 128)] = v;
                } else {
                    o2[(size_t)row*16 + (col - 144)] = v;
                }
            } else if (EPI == 2) {
                float t = v + aux0[col];
                C[idx] = t > 0.f ? t : 0.f;
            } else if (EPI == 3) {
                C[idx] = v + aux0[idx];
            } else if (EPI == 4) {
                C[idx] = v + aux0[idx] + aux1[col];
            } else if (EPI == 5) {
                C[idx] = 2.f*v - (row == col ? 1.f : 0.f);
            } else if (EPI == 6) {
                C[idx] = v + aux0[col];
            }
        }
    }
}

// ---------------- causal conv (both directions) + silu ----------------
__global__ void conv_silu_k(const float* __restrict__ xz,
                            const float* __restrict__ cw0, const float* __restrict__ cb0,
                            const float* __restrict__ cw1, const float* __restrict__ cb1,
                            float* __restrict__ xc0, float* __restrict__ xc1)
{
    int dir = blockIdx.y;
    int g = blockIdx.x * 256 + threadIdx.x;   // < 16384*128
    int d = g & 127; int m = g >> 7; int l = m & 1023;
    const float* cw = dir ? cw1 : cw0;
    const float* cb = dir ? cb1 : cb0;
    const float* src = xz + dir * 256 + d;
    float acc = cb[d];
    #pragma unroll
    for (int k = 0; k < 4; k++) {
        int ll = dir ? (l + 3 - k) : (l - 3 + k);
        if (ll >= 0 && ll < 1024)
            acc = fmaf(src[(size_t)(m - l + ll) * 512], cw[d*4 + k], acc);
    }
    (dir ? xc1 : xc0)[g] = silu_(acc);
}

// ---------------- selective scan (both directions fused) ----------------
__global__ void __launch_bounds__(512) scan_k(
    const float* __restrict__ dt0, const float* __restrict__ dt1,
    const float* __restrict__ xc0, const float* __restrict__ xc1,
    const float* __restrict__ B0,  const float* __restrict__ B1,
    const float* __restrict__ C0,  const float* __restrict__ C1,
    const float* __restrict__ xz,
    const float* __restrict__ A0,  const float* __restrict__ A1,
    const float* __restrict__ D0,  const float* __restrict__ D1,
    float* __restrict__ y0, float* __restrict__ y1)
{
    int dir = blockIdx.z;
    int b = blockIdx.y;
    int t = threadIdx.x, s = t & 15, dl = t >> 4;
    int d = blockIdx.x * 32 + dl;
    const float* dt = dir ? dt1 : dt0;
    const float* xc = dir ? xc1 : xc0;
    const float* Bm = dir ? B1 : B0;
    const float* Cm = dir ? C1 : C0;
    const float* Aa = dir ? A1 : A0;
    const float* Dp = dir ? D1 : D0;
    float* y = dir ? y1 : y0;
    float Ads = Aa[d*16 + s];
    float Dpd = Dp[d];
    const float* dtp = dt + (size_t)b*1024*128 + d;
    const float* xcp = xc + (size_t)b*1024*128 + d;
    const float* Bp  = Bm + (size_t)b*1024*16 + s;
    const float* Cp  = Cm + (size_t)b*1024*16 + s;
    const float* zp  = xz + (size_t)b*1024*512 + dir*256 + 128 + d;
    float* yp = y + (size_t)b*1024*128 + d;
    float h = 0.f;
    for (int tt = 0; tt < 1024; tt++) {
        int l = dir ? (1023 - tt) : tt;
        float dtv = dtp[(size_t)l*128];
        float xcv = xcp[(size_t)l*128];
        float Bv  = Bp[(size_t)l*16];
        float Cv  = Cp[(size_t)l*16];
        h = fmaf(h, __expf(dtv * Ads), dtv * Bv * xcv);
        float part = h * Cv;
        part += __shfl_xor_sync(0xffffffffu, part, 8);
        part += __shfl_xor_sync(0xffffffffu, part, 4);
        part += __shfl_xor_sync(0xffffffffu, part, 2);
        part += __shfl_xor_sync(0xffffffffu, part, 1);
        if (s == 0) {
            float zv = zp[(size_t)l*512];
            yp[(size_t)l*128] = (part + Dpd * xcv) * silu_(zv);
        }
    }
}

// ---------------- LayerNorm over D=64, warp per row ----------------
__global__ void ln_k(const float* __restrict__ in, const float* __restrict__ g,
                     const float* __restrict__ bb, float* __restrict__ out)
{
    int warp = threadIdx.x >> 5, lane = threadIdx.x & 31;
    int row = blockIdx.x * 8 + warp;
    const float* p = in + (size_t)row * 64;
    float v0 = p[lane], v1 = p[lane + 32];
    float sm = v0 + v1;
    #pragma unroll
    for (int o = 16; o > 0; o >>= 1) sm += __shfl_xor_sync(0xffffffffu, sm, o);
    float mean = sm * (1.f / 64.f);
    float d0 = v0 - mean, d1 = v1 - mean;
    float q = d0*d0 + d1*d1;
    #pragma unroll
    for (int o = 16; o > 0; o >>= 1) q += __shfl_xor_sync(0xffffffffu, q, o);
    float r = rsqrtf(q * (1.f / 64.f) + 1e-5f);
    out[(size_t)row*64 + lane]      = d0 * r * g[lane]      + bb[lane];
    out[(size_t)row*64 + lane + 32] = d1 * r * g[lane + 32] + bb[lane + 32];
}

// ---------------- support matrix: softmax(relu(E E^T)) ----------------
__global__ void __launch_bounds__(256) sup_k(const float* __restrict__ emb, float* __restrict__ sup)
{
    __shared__ float se[NNODE * EDIM];
    __shared__ float red[256];
    int n = blockIdx.x, tid = threadIdx.x;
    for (int i = tid; i < NNODE*EDIM; i += 256) se[i] = emb[i];
    __syncthreads();
    float en[EDIM];
    #pragma unroll
    for (int e = 0; e < EDIM; e++) en[e] = se[n*EDIM + e];
    float vals[4]; float mx = -1e30f;
    #pragma unroll
    for (int jj = 0; jj < 4; jj++) {
        int j = jj*256 + tid;
        float v = 0.f;
        #pragma unroll
        for (int e = 0; e < EDIM; e++) v = fmaf(en[e], se[j*EDIM + e], v);
        v = v > 0.f ? v : 0.f;
        vals[jj] = v; mx = fmaxf(mx, v);
    }
    red[tid] = mx; __syncthreads();
    for (int o = 128; o > 0; o >>= 1) { if (tid < o) red[tid] = fmaxf(red[tid], red[tid+o]); __syncthreads(); }
    mx = red[0]; __syncthreads();
    float s = 0.f;
    #pragma unroll
    for (int jj = 0; jj < 4; jj++) { vals[jj] = __expf(vals[jj] - mx); s += vals[jj]; }
    red[tid] = s; __syncthreads();
    for (int o = 128; o > 0; o >>= 1) { if (tid < o) red[tid] += red[tid+o]; __syncthreads(); }
    float inv = 1.f / red[0];
    #pragma unroll
    for (int jj = 0; jj < 4; jj++) sup[(size_t)n*1024 + jj*256 + tid] = vals[jj] * inv;
}

// ---------------- W[n,k,c,o] = sum_e emb[n,e] W_pool[e,k,c,o] ----------------
__global__ void wmix_k(const float* __restrict__ emb, const float* __restrict__ wp,
                       float* __restrict__ W)
{
    int n = blockIdx.y;
    int j = blockIdx.x * 256 + threadIdx.x;  // < 12288
    float acc = 0.f;
    #pragma unroll
    for (int e = 0; e < EDIM; e++) acc = fmaf(emb[n*EDIM + e], wp[(size_t)e*12288 + j], acc);
    W[(size_t)n*12288 + j] = acc;
}

// ---------------- per-node graph conv ----------------
// out[b,n,o] = sum_{k,c} xg[b,k,n,c] W[n,k,c,o] + bias[n,o]
// x tile (3*16*64 floats) in static smem; W streamed from global (read-only, L1-cached).
__global__ void __launch_bounds__(256) gconv_k(
    const float* __restrict__ x,  const float* __restrict__ xg1,
    const float* __restrict__ xg2, const float* __restrict__ W,
    const float* __restrict__ emb, const float* __restrict__ bp,
    float* __restrict__ go)
{
    __shared__ float xs[3072];
    __shared__ float bs[64];
    int n = blockIdx.x, tid = threadIdx.x;
    const float* Wn = W + (size_t)n * 12288;
    for (int i = tid; i < 3072; i += 256) {
        int k = i >> 10; int rem = i & 1023; int b = rem >> 6; int c = rem & 63;
        const float* src = (k == 0) ? x : (k == 1 ? xg1 : xg2);
        xs[i] = src[(size_t)b*65536 + (size_t)n*64 + c];
    }
    if (tid < 64) {
        float a = 0.f;
        #pragma unroll
        for (int e = 0; e < EDIM; e++) a = fmaf(emb[n*EDIM + e], bp[e*64 + tid], a);
        bs[tid] = a;
    }
    __syncthreads();
    int o = tid & 63, bq = tid >> 6;
    float acc[4];
    #pragma unroll
    for (int q = 0; q < 4; q++) acc[q] = bs[o];
    #pragma unroll 4
    for (int kc = 0; kc < 192; kc++) {
        float w = __ldg(Wn + kc*64 + o);
        int k = kc >> 6, c = kc & 63;
        #pragma unroll
        for (int q = 0; q < 4; q++)
            acc[q] = fmaf(xs[(k*16 + bq + q*4)*64 + c], w, acc[q]);
    }
    #pragma unroll
    for (int q = 0; q < 4; q++) {
        int b = bq + q*4;
        go[(size_t)b*65536 + (size_t)n*64 + o] = acc[q];
    }
}

// ---------------- launch ----------------
extern "C" void kernel_launch(void* const* d_in, const int* in_sizes, int n_in,
                              void* d_out, int out_size)
{
    const float* x_in     = (const float*)d_in[0];
    const float* fw_in    = (const float*)d_in[1];
    const float* fw_cw    = (const float*)d_in[2];
    const float* fw_cb    = (const float*)d_in[3];
    const float* fw_xp    = (const float*)d_in[4];
    const float* fw_dtw   = (const float*)d_in[5];
    const float* fw_dtb   = (const float*)d_in[6];
    const float* fw_Alog  = (const float*)d_in[7];
    const float* fw_D     = (const float*)d_in[8];
    const float* fw_out   = (const float*)d_in[9];
    const float* bw_in    = (const float*)d_in[10];
    const float* bw_cw    = (const float*)d_in[11];
    const float* bw_cb    = (const float*)d_in[12];
    const float* bw_xp    = (const float*)d_in[13];
    const float* bw_dtw   = (const float*)d_in[14];
    const float* bw_dtb   = (const float*)d_in[15];
    const float* bw_Alog  = (const float*)d_in[16];
    const float* bw_D     = (const float*)d_in[17];
    const float* bw_out   = (const float*)d_in[18];
    const float* ln1_g    = (const float*)d_in[19];
    const float* ln1_b    = (const float*)d_in[20];
    const float* ffn_w1   = (const float*)d_in[21];
    const float* ffn_b1   = (const float*)d_in[22];
    const float* ffn_w2   = (const float*)d_in[23];
    const float* ffn_b2   = (const float*)d_in[24];
    const float* ln2_g    = (const float*)d_in[25];
    const float* ln2_b    = (const float*)d_in[26];
    const float* node_emb = (const float*)d_in[27];
    const float* W_pool   = (const float*)d_in[28];
    const float* b_pool   = (const float*)d_in[29];
    const float* proj_w   = (const float*)d_in[30];
    const float* proj_b   = (const float*)d_in[31];
    float* outp = (float*)d_out;

    float* S = nullptr;
    cudaGetSymbolAddress((void**)&S, g_scratch);

    float* Wcat   = S;
    float* Wcomb0 = S + 32768;
    float* Wcomb1 = S + 53248;
    float* A0     = S + 73728;
    float* A1     = S + 75776;
    float* xz     = S + 77824;
    float* xc0    = S + 8466432;
    float* xc1    = S + 10563584;
    float* dt0    = S + 12660736;
    float* dt1    = S + 14757888;
    float* Bm0    = S + 16855040;
    float* Bm1    = S + 17117184;
    float* Cm0    = S + 17379328;
    float* Cm1    = S + 17641472;
    float* y0     = S + 17903616;
    float* y1     = S + 20000768;
    float* xbuf   = S + 22097920;
    float* t1     = S + 23146496;
    float* t2     = S + 24195072;
    float* hbuf   = S + 25243648;
    float* sup    = S + 29437952;
    float* cheb   = S + 30486528;
    float* xg1    = S + 31535104;
    float* xg2    = S + 32583680;
    float* Wbig   = S + 33632256;
    float* go     = S + 46215168;

    // prep: weights + x copy
    {
        int total = 77824 + MROWS*DMODEL;
        prep_k<<<(total + 255)/256, 256>>>(fw_in, bw_in, fw_xp, fw_dtw, bw_xp, bw_dtw,
                                           fw_Alog, bw_Alog, x_in,
                                           Wcat, Wcomb0, Wcomb1, A0, A1, xbuf);
    }

    for (int layer = 0; layer < 2; layer++) {
        // xz = x @ [fw_in | bw_in]   (16384 x 512)
        sgemm_k<0><<<dim3(8, 256, 1), 256>>>(xbuf, Wcat, xz, MROWS, 512, 64,
                                             0, 0, 0, nullptr, nullptr, nullptr, nullptr);
        // conv + silu, both dirs
        conv_silu_k<<<dim3((MROWS*128)/256, 2, 1), 256>>>(xz, fw_cw, fw_cb, bw_cw, bw_cb, xc0, xc1);
        // xproj -> dt (softplus), Bm, Cm
        sgemm_k<1><<<dim3(3, 256, 1), 256>>>(xc0, Wcomb0, dt0, MROWS, 160, 128,
                                             0, 0, 0, fw_dtb, nullptr, Bm0, Cm0);
        sgemm_k<1><<<dim3(3, 256, 1), 256>>>(xc1, Wcomb1, dt1, MROWS, 160, 128,
                                             0, 0, 0, bw_dtb, nullptr, Bm1, Cm1);
        // selective scan, both dirs fused
        scan_k<<<dim3(4, 16, 2), 512>>>(dt0, dt1, xc0, xc1, Bm0, Bm1, Cm0, Cm1,
                                        xz, A0, A1, fw_D, bw_D, y0, y1);
        // x + yf@Wo_f + yb@Wo_b
        sgemm_k<3><<<dim3(1, 256, 1), 256>>>(y0, fw_out, t1, MROWS, 64, 128,
                                             0, 0, 0, xbuf, nullptr, nullptr, nullptr);
        sgemm_k<3><<<dim3(1, 256, 1), 256>>>(y1, bw_out, t2, MROWS, 64, 128,
                                             0, 0, 0, t1, nullptr, nullptr, nullptr);
        ln_k<<<MROWS/8, 256>>>(t2, ln1_g, ln1_b, xbuf);
        // FFN
        sgemm_k<2><<<dim3(4, 256, 1), 256>>>(xbuf, ffn_w1, hbuf, MROWS, 256, 64,
                                             0, 0, 0, ffn_b1, nullptr, nullptr, nullptr);
        sgemm_k<4><<<dim3(1, 256, 1), 256>>>(hbuf, ffn_w2, t1, MROWS, 64, 256,
                                             0, 0, 0, xbuf, ffn_b2, nullptr, nullptr);
        ln_k<<<MROWS/8, 256>>>(t1, ln2_g, ln2_b, xbuf);
    }

    // graph part
    sup_k<<<NNODE, 256>>>(node_emb, sup);
    // cheb2 = 2*sup@sup - I
    sgemm_k<5><<<dim3(16, 16, 1), 256>>>(sup, sup, cheb, 1024, 1024, 1024,
                                         0, 0, 0, nullptr, nullptr, nullptr, nullptr);
    // xg1[b] = sup @ x_b ; xg2[b] = cheb2 @ x_b  (batched over b)
    sgemm_k<0><<<dim3(1, 16, 16), 256>>>(sup, xbuf, xg1, 1024, 64, 1024,
                                         0, 65536, 65536, nullptr, nullptr, nullptr, nullptr);
    sgemm_k<0><<<dim3(1, 16, 16), 256>>>(cheb, xbuf, xg2, 1024, 64, 1024,
                                         0, 65536, 65536, nullptr, nullptr, nullptr, nullptr);
    // mixed weights
    wmix_k<<<dim3(48, 1024, 1), 256>>>(node_emb, W_pool, Wbig);
    // per-node contraction
    gconv_k<<<NNODE, 256>>>(xbuf, xg1, xg2, Wbig, node_emb, b_pool, go);
    // final projection + bias -> d_out
    sgemm_k<6><<<dim3(2, 256, 1), 256>>>(go, proj_w, outp, MROWS, PLOUT, 64,
                                         0, 0, 0, proj_b, nullptr, nullptr, nullptr);
}

// round 6
// speedup vs baseline: 1.4800x; 1.4800x over previous
#include <cuda_runtime.h>
#include <math.h>

// ---------------- problem constants ----------------
#define BATCH   16
#define LSEQ    1024
#define DMODEL  64
#define DINNER  128
#define SSTATE  16
#define MROWS   (BATCH*LSEQ)   // 16384
#define HFFN    256
#define NNODE   1024
#define EDIM    10
#define PLOUT   96

// ---------------- scratch (single static device buffer) ----------------
__device__ float g_scratch[47280128];

__device__ __forceinline__ float silu_(float x) { return x / (1.f + __expf(-x)); }

// ---------------- prep: fold weights, A = -exp(Alog), copy x ----------------
__global__ void prep_k(const float* __restrict__ fw_in, const float* __restrict__ bw_in,
                       const float* __restrict__ fwx, const float* __restrict__ fwdt,
                       const float* __restrict__ bwx, const float* __restrict__ bwdt,
                       const float* __restrict__ fwA, const float* __restrict__ bwA,
                       const float* __restrict__ fw_out, const float* __restrict__ bw_out,
                       const float* __restrict__ x_in,
                       float* __restrict__ Wcat, float* __restrict__ Wcomb0,
                       float* __restrict__ Wcomb1, float* __restrict__ A0,
                       float* __restrict__ A1, float* __restrict__ Wocat,
                       float* __restrict__ xbuf)
{
    int g = blockIdx.x * 256 + threadIdx.x;
    if (g < 32768) {  // Wcat (64,512)
        int k = g >> 9, j = g & 511;
        Wcat[g] = (j < 256) ? fw_in[k*256 + j] : bw_in[k*256 + (j-256)];
        return;
    }
    int h = g - 32768;
    if (h < 40960) {  // Wcomb (2 x 128 x 160)
        int dir = h / 20480; int r2 = h % 20480;
        int i = r2 / 160, j = r2 % 160;
        const float* Wx  = dir ? bwx  : fwx;
        const float* Wdt = dir ? bwdt : fwdt;
        float v;
        if (j < 128) {
            v = 0.f;
            #pragma unroll
            for (int r = 0; r < 4; r++) v = fmaf(Wx[i*36 + r], Wdt[r*128 + j], v);
        } else {
            v = Wx[i*36 + 4 + (j - 128)];
        }
        (dir ? Wcomb1 : Wcomb0)[i*160 + j] = v;
        return;
    }
    h -= 40960;
    if (h < 4096) {  // A
        int dir = h >> 11; int i = h & 2047;
        (dir ? A1 : A0)[i] = -__expf((dir ? bwA : fwA)[i]);
        return;
    }
    h -= 4096;
    if (h < 16384) {  // Wocat (256,64): rows 0-127 fw_out, 128-255 bw_out
        int r = h >> 6, c = h & 63;
        Wocat[h] = (r < 128) ? fw_out[r*64 + c] : bw_out[(r-128)*64 + c];
        return;
    }
    h -= 16384;
    if (h < MROWS*DMODEL) xbuf[h] = x_in[h];
}

// ---------------- generic tiled SGEMM, double-buffered smem, with epilogues --------
// EPI: 0 store, 1 xproj-split(softplus dt | Bm | Cm), 2 bias+relu, 3 +aux0(full),
//      4 +aux0(full)+aux1(col), 5 2v - I, 6 +aux0(col)
template<int EPI>
__global__ void __launch_bounds__(256) sgemm_k(
    const float* __restrict__ A, const float* __restrict__ B, float* __restrict__ C,
    int M, int N, int K, long long sA, long long sB, long long sC,
    const float* __restrict__ aux0, const float* __restrict__ aux1,
    float* __restrict__ o1, float* __restrict__ o2)
{
    __shared__ float As[2][16][64];
    __shared__ float Bs[2][16][64];
    int bz = blockIdx.z;
    A += sA * bz; B += sB * bz; C += sC * bz;
    int row0 = blockIdx.y * 64, col0 = blockIdx.x * 64;
    int tid = threadIdx.x;
    int tx = tid & 15, ty = tid >> 4;
    int a_m = tid >> 2, a_k = (tid & 3) * 4;
    int b_k = tid >> 4, b_n = (tid & 15) * 4;
    const float* Aptr = A + (size_t)(row0 + a_m) * K + a_k;
    int bc = col0 + b_n;
    bool bok = bc < N;
    const float* Bptr = B + (size_t)b_k * N + bc;

    float acc[4][4];
    #pragma unroll
    for (int i = 0; i < 4; i++)
        #pragma unroll
        for (int j = 0; j < 4; j++) acc[i][j] = 0.f;

    // preload tile 0
    {
        float4 av = *(const float4*)(Aptr);
        float4 bv = bok ? *(const float4*)(Bptr) : make_float4(0.f,0.f,0.f,0.f);
        As[0][a_k+0][a_m] = av.x; As[0][a_k+1][a_m] = av.y;
        As[0][a_k+2][a_m] = av.z; As[0][a_k+3][a_m] = av.w;
        *(float4*)&Bs[0][b_k][b_n] = bv;
    }
    __syncthreads();

    int buf = 0;
    for (int k0 = 16; ; k0 += 16) {
        bool has = (k0 < K);
        float4 av2, bv2;
        if (has) {
            av2 = *(const float4*)(Aptr + k0);
            bv2 = bok ? *(const float4*)(Bptr + (size_t)k0 * N) : make_float4(0.f,0.f,0.f,0.f);
        }
        #pragma unroll
        for (int kk = 0; kk < 16; kk++) {
            float am[4], bn[4];
            *(float4*)am = *(const float4*)&As[buf][kk][ty*4];
            *(float4*)bn = *(const float4*)&Bs[buf][kk][tx*4];
            #pragma unroll
            for (int i = 0; i < 4; i++)
                #pragma unroll
                for (int j = 0; j < 4; j++)
                    acc[i][j] = fmaf(am[i], bn[j], acc[i][j]);
        }
        if (!has) break;
        int nb = buf ^ 1;
        As[nb][a_k+0][a_m] = av2.x; As[nb][a_k+1][a_m] = av2.y;
        As[nb][a_k+2][a_m] = av2.z; As[nb][a_k+3][a_m] = av2.w;
        *(float4*)&Bs[nb][b_k][b_n] = bv2;
        __syncthreads();
        buf = nb;
    }

    #pragma unroll
    for (int i = 0; i < 4; i++) {
        int row = row0 + ty*4 + i;
        #pragma unroll
        for (int j = 0; j < 4; j++) {
            int col = col0 + tx*4 + j;
            if (col >= N) continue;
            float v = acc[i][j];
            size_t idx = (size_t)row * N + col;
            if (EPI == 0) {
                C[idx] = v;
            } else if (EPI == 1) {
                if (col < 128) {
                    float t = v + aux0[col];
                    C[(size_t)row*128 + col] = (t > 20.f) ? t : log1pf(__expf(t));
                } else if (col < 144) {
                    o1[(size_t)row*16 + (col - 128)] = v;
                } else {
                    o2[(size_t)row*16 + (col - 144)] = v;
                }
            } else if (EPI == 2) {
                float t = v + aux0[col];
                C[idx] = t > 0.f ? t : 0.f;
            } else if (EPI == 3) {
                C[idx] = v + aux0[idx];
            } else if (EPI == 4) {
                C[idx] = v + aux0[idx] + aux1[col];
            } else if (EPI == 5) {
                C[idx] = 2.f*v - (row == col ? 1.f : 0.f);
            } else if (EPI == 6) {
                C[idx] = v + aux0[col];
            }
        }
    }
}

// ---------------- causal conv (both directions) + silu ----------------
__global__ void conv_silu_k(const float* __restrict__ xz,
                            const float* __restrict__ cw0, const float* __restrict__ cb0,
                            const float* __restrict__ cw1, const float* __restrict__ cb1,
                            float* __restrict__ xc0, float* __restrict__ xc1)
{
    int dir = blockIdx.y;
    int g = blockIdx.x * 256 + threadIdx.x;   // < 16384*128
    int d = g & 127; int m = g >> 7; int l = m & 1023;
    const float* cw = dir ? cw1 : cw0;
    const float* cb = dir ? cb1 : cb0;
    const float* src = xz + dir * 256 + d;
    float acc = cb[d];
    #pragma unroll
    for (int k = 0; k < 4; k++) {
        int ll = dir ? (l + 3 - k) : (l - 3 + k);
        if (ll >= 0 && ll < 1024)
            acc = fmaf(src[(size_t)(m - l + ll) * 512], cw[d*4 + k], acc);
    }
    (dir ? xc1 : xc0)[g] = silu_(acc);
}

// ---------------- selective scan (both directions fused, software-pipelined) -------
// writes into ycat (M,256): cols [dir*128 + d]
__global__ void __launch_bounds__(512) scan_k(
    const float* __restrict__ dt0, const float* __restrict__ dt1,
    const float* __restrict__ xc0, const float* __restrict__ xc1,
    const float* __restrict__ B0,  const float* __restrict__ B1,
    const float* __restrict__ C0,  const float* __restrict__ C1,
    const float* __restrict__ xz,
    const float* __restrict__ A0,  const float* __restrict__ A1,
    const float* __restrict__ D0,  const float* __restrict__ D1,
    float* __restrict__ ycat)
{
    int dir = blockIdx.z;
    int b = blockIdx.y;
    int t = threadIdx.x, s = t & 15, dl = t >> 4;
    int d = blockIdx.x * 32 + dl;
    const float* dt = dir ? dt1 : dt0;
    const float* xc = dir ? xc1 : xc0;
    const float* Bm = dir ? B1 : B0;
    const float* Cm = dir ? C1 : C0;
    const float* Aa = dir ? A1 : A0;
    const float* Dp = dir ? D1 : D0;
    float Ads = Aa[d*16 + s];
    float Dpd = Dp[d];

    int l0  = dir ? 1023 : 0;
    int stp = dir ? -1 : 1;
    const float* pdt = dt + (size_t)b*1024*128 + (size_t)l0*128 + d;
    const float* pxc = xc + (size_t)b*1024*128 + (size_t)l0*128 + d;
    const float* pB  = Bm + (size_t)b*1024*16  + (size_t)l0*16  + s;
    const float* pC  = Cm + (size_t)b*1024*16  + (size_t)l0*16  + s;
    const float* pz  = xz + (size_t)b*1024*512 + (size_t)l0*512 + dir*256 + 128 + d;
    float* py        = ycat + (size_t)b*1024*256 + (size_t)l0*256 + dir*128 + d;
    int d128 = stp*128, d16 = stp*16, d512 = stp*512, d256 = stp*256;

    float dtv = *pdt, xcv = *pxc, Bv = *pB, Cv = *pC, zv = *pz;
    float h = 0.f;
    for (int tt = 0; tt < 1024; tt++) {
        float e   = __expf(dtv * Ads);
        float dBx = dtv * Bv * xcv;
        float dtv2, xcv2, Bv2, Cv2, zv2;
        if (tt < 1023) {
            dtv2 = pdt[d128]; xcv2 = pxc[d128];
            Bv2  = pB[d16];   Cv2  = pC[d16];
            zv2  = pz[d512];
        } else { dtv2 = xcv2 = Bv2 = Cv2 = zv2 = 0.f; }
        h = fmaf(h, e, dBx);
        float part = h * Cv;
        part += __shfl_xor_sync(0xffffffffu, part, 8);
        part += __shfl_xor_sync(0xffffffffu, part, 4);
        part += __shfl_xor_sync(0xffffffffu, part, 2);
        part += __shfl_xor_sync(0xffffffffu, part, 1);
        if (s == 0)
            py[0] = (part + Dpd * xcv) * silu_(zv);
        pdt += d128; pxc += d128; pB += d16; pC += d16; pz += d512; py += d256;
        dtv = dtv2; xcv = xcv2; Bv = Bv2; Cv = Cv2; zv = zv2;
    }
}

// ---------------- LayerNorm over D=64, warp per row ----------------
__global__ void ln_k(const float* __restrict__ in, const float* __restrict__ g,
                     const float* __restrict__ bb, float* __restrict__ out)
{
    int warp = threadIdx.x >> 5, lane = threadIdx.x & 31;
    int row = blockIdx.x * 8 + warp;
    const float* p = in + (size_t)row * 64;
    float v0 = p[lane], v1 = p[lane + 32];
    float sm = v0 + v1;
    #pragma unroll
    for (int o = 16; o > 0; o >>= 1) sm += __shfl_xor_sync(0xffffffffu, sm, o);
    float mean = sm * (1.f / 64.f);
    float d0 = v0 - mean, d1 = v1 - mean;
    float q = d0*d0 + d1*d1;
    #pragma unroll
    for (int o = 16; o > 0; o >>= 1) q += __shfl_xor_sync(0xffffffffu, q, o);
    float r = rsqrtf(q * (1.f / 64.f) + 1e-5f);
    out[(size_t)row*64 + lane]      = d0 * r * g[lane]      + bb[lane];
    out[(size_t)row*64 + lane + 32] = d1 * r * g[lane + 32] + bb[lane + 32];
}

// ---------------- support matrix: softmax(relu(E E^T)) ----------------
__global__ void __launch_bounds__(256) sup_k(const float* __restrict__ emb, float* __restrict__ sup)
{
    __shared__ float se[NNODE * EDIM];
    __shared__ float red[256];
    int n = blockIdx.x, tid = threadIdx.x;
    for (int i = tid; i < NNODE*EDIM; i += 256) se[i] = emb[i];
    __syncthreads();
    float en[EDIM];
    #pragma unroll
    for (int e = 0; e < EDIM; e++) en[e] = se[n*EDIM + e];
    float vals[4]; float mx = -1e30f;
    #pragma unroll
    for (int jj = 0; jj < 4; jj++) {
        int j = jj*256 + tid;
        float v = 0.f;
        #pragma unroll
        for (int e = 0; e < EDIM; e++) v = fmaf(en[e], se[j*EDIM + e], v);
        v = v > 0.f ? v : 0.f;
        vals[jj] = v; mx = fmaxf(mx, v);
    }
    red[tid] = mx; __syncthreads();
    for (int o = 128; o > 0; o >>= 1) { if (tid < o) red[tid] = fmaxf(red[tid], red[tid+o]); __syncthreads(); }
    mx = red[0]; __syncthreads();
    float s = 0.f;
    #pragma unroll
    for (int jj = 0; jj < 4; jj++) { vals[jj] = __expf(vals[jj] - mx); s += vals[jj]; }
    red[tid] = s; __syncthreads();
    for (int o = 128; o > 0; o >>= 1) { if (tid < o) red[tid] += red[tid+o]; __syncthreads(); }
    float inv = 1.f / red[0];
    #pragma unroll
    for (int jj = 0; jj < 4; jj++) sup[(size_t)n*1024 + jj*256 + tid] = vals[jj] * inv;
}

// ---------------- W[n,k,c,o] = sum_e emb[n,e] W_pool[e,k,c,o] ----------------
__global__ void wmix_k(const float* __restrict__ emb, const float* __restrict__ wp,
                       float* __restrict__ W)
{
    int n = blockIdx.y;
    int j = blockIdx.x * 256 + threadIdx.x;  // < 12288
    float acc = 0.f;
    #pragma unroll
    for (int e = 0; e < EDIM; e++) acc = fmaf(emb[n*EDIM + e], wp[(size_t)e*12288 + j], acc);
    W[(size_t)n*12288 + j] = acc;
}

// ---------------- per-node graph conv ----------------
__global__ void __launch_bounds__(256) gconv_k(
    const float* __restrict__ x,  const float* __restrict__ xg1,
    const float* __restrict__ xg2, const float* __restrict__ W,
    const float* __restrict__ emb, const float* __restrict__ bp,
    float* __restrict__ go)
{
    __shared__ float xs[3072];
    __shared__ float bs[64];
    int n = blockIdx.x, tid = threadIdx.x;
    const float* Wn = W + (size_t)n * 12288;
    for (int i = tid; i < 3072; i += 256) {
        int k = i >> 10; int rem = i & 1023; int b = rem >> 6; int c = rem & 63;
        const float* src = (k == 0) ? x : (k == 1 ? xg1 : xg2);
        xs[i] = src[(size_t)b*65536 + (size_t)n*64 + c];
    }
    if (tid < 64) {
        float a = 0.f;
        #pragma unroll
        for (int e = 0; e < EDIM; e++) a = fmaf(emb[n*EDIM + e], bp[e*64 + tid], a);
        bs[tid] = a;
    }
    __syncthreads();
    int o = tid & 63, bq = tid >> 6;
    float acc[4];
    #pragma unroll
    for (int q = 0; q < 4; q++) acc[q] = bs[o];
    #pragma unroll 4
    for (int kc = 0; kc < 192; kc++) {
        float w = __ldg(Wn + kc*64 + o);
        int k = kc >> 6, c = kc & 63;
        #pragma unroll
        for (int q = 0; q < 4; q++)
            acc[q] = fmaf(xs[(k*16 + bq + q*4)*64 + c], w, acc[q]);
    }
    #pragma unroll
    for (int q = 0; q < 4; q++) {
        int b = bq + q*4;
        go[(size_t)b*65536 + (size_t)n*64 + o] = acc[q];
    }
}

// ---------------- launch ----------------
extern "C" void kernel_launch(void* const* d_in, const int* in_sizes, int n_in,
                              void* d_out, int out_size)
{
    const float* x_in     = (const float*)d_in[0];
    const float* fw_in    = (const float*)d_in[1];
    const float* fw_cw    = (const float*)d_in[2];
    const float* fw_cb    = (const float*)d_in[3];
    const float* fw_xp    = (const float*)d_in[4];
    const float* fw_dtw   = (const float*)d_in[5];
    const float* fw_dtb   = (const float*)d_in[6];
    const float* fw_Alog  = (const float*)d_in[7];
    const float* fw_D     = (const float*)d_in[8];
    const float* fw_out   = (const float*)d_in[9];
    const float* bw_in    = (const float*)d_in[10];
    const float* bw_cw    = (const float*)d_in[11];
    const float* bw_cb    = (const float*)d_in[12];
    const float* bw_xp    = (const float*)d_in[13];
    const float* bw_dtw   = (const float*)d_in[14];
    const float* bw_dtb   = (const float*)d_in[15];
    const float* bw_Alog  = (const float*)d_in[16];
    const float* bw_D     = (const float*)d_in[17];
    const float* bw_out   = (const float*)d_in[18];
    const float* ln1_g    = (const float*)d_in[19];
    const float* ln1_b    = (const float*)d_in[20];
    const float* ffn_w1   = (const float*)d_in[21];
    const float* ffn_b1   = (const float*)d_in[22];
    const float* ffn_w2   = (const float*)d_in[23];
    const float* ffn_b2   = (const float*)d_in[24];
    const float* ln2_g    = (const float*)d_in[25];
    const float* ln2_b    = (const float*)d_in[26];
    const float* node_emb = (const float*)d_in[27];
    const float* W_pool   = (const float*)d_in[28];
    const float* b_pool   = (const float*)d_in[29];
    const float* proj_w   = (const float*)d_in[30];
    const float* proj_b   = (const float*)d_in[31];
    float* outp = (float*)d_out;

    float* S = nullptr;
    cudaGetSymbolAddress((void**)&S, g_scratch);

    float* Wcat   = S;
    float* Wcomb0 = S + 32768;
    float* Wcomb1 = S + 53248;
    float* A0     = S + 73728;
    float* A1     = S + 75776;
    float* xz     = S + 77824;
    float* xc0    = S + 8466432;
    float* xc1    = S + 10563584;
    float* dt0    = S + 12660736;
    float* dt1    = S + 14757888;
    float* Bm0    = S + 16855040;
    float* Bm1    = S + 17117184;
    float* Cm0    = S + 17379328;
    float* Cm1    = S + 17641472;
    float* ycat   = S + 17903616;   // (M,256) = 4,194,304 floats
    float* xbuf   = S + 22097920;
    float* t1     = S + 23146496;
    float* hbuf   = S + 25243648;
    float* sup    = S + 29437952;
    float* cheb   = S + 30486528;
    float* xg1    = S + 31535104;
    float* xg2    = S + 32583680;
    float* Wbig   = S + 33632256;
    float* go     = S + 46215168;
    float* Wocat  = S + 47263744;   // (256,64)

    // prep: weights + x copy
    {
        int total = 32768 + 40960 + 4096 + 16384 + MROWS*DMODEL;
        prep_k<<<(total + 255)/256, 256>>>(fw_in, bw_in, fw_xp, fw_dtw, bw_xp, bw_dtw,
                                           fw_Alog, bw_Alog, fw_out, bw_out, x_in,
                                           Wcat, Wcomb0, Wcomb1, A0, A1, Wocat, xbuf);
    }

    for (int layer = 0; layer < 2; layer++) {
        // xz = x @ [fw_in | bw_in]   (16384 x 512)
        sgemm_k<0><<<dim3(8, 256, 1), 256>>>(xbuf, Wcat, xz, MROWS, 512, 64,
                                             0, 0, 0, nullptr, nullptr, nullptr, nullptr);
        // conv + silu, both dirs
        conv_silu_k<<<dim3((MROWS*128)/256, 2, 1), 256>>>(xz, fw_cw, fw_cb, bw_cw, bw_cb, xc0, xc1);
        // xproj -> dt (softplus), Bm, Cm
        sgemm_k<1><<<dim3(3, 256, 1), 256>>>(xc0, Wcomb0, dt0, MROWS, 160, 128,
                                             0, 0, 0, fw_dtb, nullptr, Bm0, Cm0);
        sgemm_k<1><<<dim3(3, 256, 1), 256>>>(xc1, Wcomb1, dt1, MROWS, 160, 128,
                                             0, 0, 0, bw_dtb, nullptr, Bm1, Cm1);
        // selective scan, both dirs fused -> ycat
        scan_k<<<dim3(4, 16, 2), 512>>>(dt0, dt1, xc0, xc1, Bm0, Bm1, Cm0, Cm1,
                                        xz, A0, A1, fw_D, bw_D, ycat);
        // x + [yf|yb] @ Wocat  (single K=256 GEMM)
        sgemm_k<3><<<dim3(1, 256, 1), 256>>>(ycat, Wocat, t1, MROWS, 64, 256,
                                             0, 0, 0, xbuf, nullptr, nullptr, nullptr);
        ln_k<<<MROWS/8, 256>>>(t1, ln1_g, ln1_b, xbuf);
        // FFN
        sgemm_k<2><<<dim3(4, 256, 1), 256>>>(xbuf, ffn_w1, hbuf, MROWS, 256, 64,
                                             0, 0, 0, ffn_b1, nullptr, nullptr, nullptr);
        sgemm_k<4><<<dim3(1, 256, 1), 256>>>(hbuf, ffn_w2, t1, MROWS, 64, 256,
                                             0, 0, 0, xbuf, ffn_b2, nullptr, nullptr);
        ln_k<<<MROWS/8, 256>>>(t1, ln2_g, ln2_b, xbuf);
    }

    // graph part
    sup_k<<<NNODE, 256>>>(node_emb, sup);
    // cheb2 = 2*sup@sup - I
    sgemm_k<5><<<dim3(16, 16, 1), 256>>>(sup, sup, cheb, 1024, 1024, 1024,
                                         0, 0, 0, nullptr, nullptr, nullptr, nullptr);
    // xg1[b] = sup @ x_b ; xg2[b] = cheb2 @ x_b  (batched over b)
    sgemm_k<0><<<dim3(1, 16, 16), 256>>>(sup, xbuf, xg1, 1024, 64, 1024,
                                         0, 65536, 65536, nullptr, nullptr, nullptr, nullptr);
    sgemm_k<0><<<dim3(1, 16, 16), 256>>>(cheb, xbuf, xg2, 1024, 64, 1024,
                                         0, 65536, 65536, nullptr, nullptr, nullptr, nullptr);
    // mixed weights
    wmix_k<<<dim3(48, 1024, 1), 256>>>(node_emb, W_pool, Wbig);
    // per-node contraction
    gconv_k<<<NNODE, 256>>>(xbuf, xg1, xg2, Wbig, node_emb, b_pool, go);
    // final projection + bias -> d_out
    sgemm_k<6><<<dim3(2, 256, 1), 256>>>(go, proj_w, outp, MROWS, PLOUT, 64,
                                         0, 0, 0, proj_b, nullptr, nullptr, nullptr);
}

// round 7
// speedup vs baseline: 1.7892x; 1.2090x over previous
#include <cuda_runtime.h>
#include <math.h>

// ---------------- problem constants ----------------
#define BATCH   16
#define LSEQ    1024
#define DMODEL  64
#define DINNER  128
#define SSTATE  16
#define MROWS   (BATCH*LSEQ)   // 16384
#define HFFN    256
#define NNODE   1024
#define EDIM    10
#define PLOUT   96
#define NCHUNK  8
#define CHLEN   128

// ---------------- scratch (single static device buffer) ----------------
__device__ float g_scratch[48852992];

__device__ __forceinline__ float silu_(float x) { return x / (1.f + __expf(-x)); }

// ---------------- prep: fold weights, A = -exp(Alog), copy x ----------------
__global__ void prep_k(const float* __restrict__ fw_in, const float* __restrict__ bw_in,
                       const float* __restrict__ fwx, const float* __restrict__ fwdt,
                       const float* __restrict__ bwx, const float* __restrict__ bwdt,
                       const float* __restrict__ fwA, const float* __restrict__ bwA,
                       const float* __restrict__ fw_out, const float* __restrict__ bw_out,
                       const float* __restrict__ x_in,
                       float* __restrict__ Wcat, float* __restrict__ Wcomb0,
                       float* __restrict__ Wcomb1, float* __restrict__ A0,
                       float* __restrict__ A1, float* __restrict__ Wocat,
                       float* __restrict__ xbuf)
{
    int g = blockIdx.x * 256 + threadIdx.x;
    if (g < 32768) {  // Wcat (64,512)
        int k = g >> 9, j = g & 511;
        Wcat[g] = (j < 256) ? fw_in[k*256 + j] : bw_in[k*256 + (j-256)];
        return;
    }
    int h = g - 32768;
    if (h < 40960) {  // Wcomb (2 x 128 x 160)
        int dir = h / 20480; int r2 = h % 20480;
        int i = r2 / 160, j = r2 % 160;
        const float* Wx  = dir ? bwx  : fwx;
        const float* Wdt = dir ? bwdt : fwdt;
        float v;
        if (j < 128) {
            v = 0.f;
            #pragma unroll
            for (int r = 0; r < 4; r++) v = fmaf(Wx[i*36 + r], Wdt[r*128 + j], v);
        } else {
            v = Wx[i*36 + 4 + (j - 128)];
        }
        (dir ? Wcomb1 : Wcomb0)[i*160 + j] = v;
        return;
    }
    h -= 40960;
    if (h < 4096) {  // A
        int dir = h >> 11; int i = h & 2047;
        (dir ? A1 : A0)[i] = -__expf((dir ? bwA : fwA)[i]);
        return;
    }
    h -= 4096;
    if (h < 16384) {  // Wocat (256,64): rows 0-127 fw_out, 128-255 bw_out
        int r = h >> 6, c = h & 63;
        Wocat[h] = (r < 128) ? fw_out[r*64 + c] : bw_out[(r-128)*64 + c];
        return;
    }
    h -= 16384;
    if (h < MROWS*DMODEL) xbuf[h] = x_in[h];
}

// ---------------- generic tiled SGEMM, double-buffered smem, with epilogues --------
// EPI: 0 store, 1 xproj-split(softplus dt | Bm | Cm), 2 bias+relu, 3 +aux0(full),
//      4 +aux0(full)+aux1(col), 5 2v - I, 6 +aux0(col),
//      7 +aux0(full) then LayerNorm(g=o1,b=o2)   [requires N==64, grid.x==1]
//      8 +aux0(full)+aux1(col) then LayerNorm(g=o1,b=o2) [requires N==64, grid.x==1]
template<int EPI>
__global__ void __launch_bounds__(256) sgemm_k(
    const float* __restrict__ A, const float* __restrict__ B, float* __restrict__ C,
    int M, int N, int K, long long sA, long long sB, long long sC,
    const float* __restrict__ aux0, const float* __restrict__ aux1,
    float* __restrict__ o1, float* __restrict__ o2)
{
    __shared__ float As[2][16][64];
    __shared__ float Bs[2][16][64];
    int bz = blockIdx.z;
    A += sA * bz; B += sB * bz; C += sC * bz;
    int row0 = blockIdx.y * 64, col0 = blockIdx.x * 64;
    int tid = threadIdx.x;
    int tx = tid & 15, ty = tid >> 4;
    int a_m = tid >> 2, a_k = (tid & 3) * 4;
    int b_k = tid >> 4, b_n = (tid & 15) * 4;
    const float* Aptr = A + (size_t)(row0 + a_m) * K + a_k;
    int bc = col0 + b_n;
    bool bok = bc < N;
    const float* Bptr = B + (size_t)b_k * N + bc;

    float acc[4][4];
    #pragma unroll
    for (int i = 0; i < 4; i++)
        #pragma unroll
        for (int j = 0; j < 4; j++) acc[i][j] = 0.f;

    // preload tile 0
    {
        float4 av = *(const float4*)(Aptr);
        float4 bv = bok ? *(const float4*)(Bptr) : make_float4(0.f,0.f,0.f,0.f);
        As[0][a_k+0][a_m] = av.x; As[0][a_k+1][a_m] = av.y;
        As[0][a_k+2][a_m] = av.z; As[0][a_k+3][a_m] = av.w;
        *(float4*)&Bs[0][b_k][b_n] = bv;
    }
    __syncthreads();

    int buf = 0;
    for (int k0 = 16; ; k0 += 16) {
        bool has = (k0 < K);
        float4 av2, bv2;
        if (has) {
            av2 = *(const float4*)(Aptr + k0);
            bv2 = bok ? *(const float4*)(Bptr + (size_t)k0 * N) : make_float4(0.f,0.f,0.f,0.f);
        }
        #pragma unroll
        for (int kk = 0; kk < 16; kk++) {
            float am[4], bn[4];
            *(float4*)am = *(const float4*)&As[buf][kk][ty*4];
            *(float4*)bn = *(const float4*)&Bs[buf][kk][tx*4];
            #pragma unroll
            for (int i = 0; i < 4; i++)
                #pragma unroll
                for (int j = 0; j < 4; j++)
                    acc[i][j] = fmaf(am[i], bn[j], acc[i][j]);
        }
        if (!has) break;
        int nb = buf ^ 1;
        As[nb][a_k+0][a_m] = av2.x; As[nb][a_k+1][a_m] = av2.y;
        As[nb][a_k+2][a_m] = av2.z; As[nb][a_k+3][a_m] = av2.w;
        *(float4*)&Bs[nb][b_k][b_n] = bv2;
        __syncthreads();
        buf = nb;
    }

    if (EPI == 7 || EPI == 8) {
        // residual(+bias) then fused LayerNorm over the full row (N==64, one tile/row)
        float vv[4][4];
        #pragma unroll
        for (int i = 0; i < 4; i++) {
            int row = row0 + ty*4 + i;
            #pragma unroll
            for (int j = 0; j < 4; j++) {
                int col = tx*4 + j;
                float v = acc[i][j] + aux0[(size_t)row*64 + col];
                if (EPI == 8) v += aux1[col];
                vv[i][j] = v;
            }
        }
        #pragma unroll
        for (int i = 0; i < 4; i++) {
            float sm = vv[i][0] + vv[i][1] + vv[i][2] + vv[i][3];
            float sq = vv[i][0]*vv[i][0] + vv[i][1]*vv[i][1]
                     + vv[i][2]*vv[i][2] + vv[i][3]*vv[i][3];
            #pragma unroll
            for (int o = 8; o > 0; o >>= 1) {
                sm += __shfl_xor_sync(0xffffffffu, sm, o);
                sq += __shfl_xor_sync(0xffffffffu, sq, o);
            }
            float mean = sm * (1.f/64.f);
            float var  = sq * (1.f/64.f) - mean*mean;
            float r = rsqrtf(var + 1e-5f);
            int row = row0 + ty*4 + i;
            #pragma unroll
            for (int j = 0; j < 4; j++) {
                int col = tx*4 + j;
                C[(size_t)row*64 + col] = (vv[i][j] - mean) * r * o1[col] + o2[col];
            }
        }
        return;
    }

    #pragma unroll
    for (int i = 0; i < 4; i++) {
        int row = row0 + ty*4 + i;
        #pragma unroll
        for (int j = 0; j < 4; j++) {
            int col = col0 + tx*4 + j;
            if (col >= N) continue;
            float v = acc[i][j];
            size_t idx = (size_t)row * N + col;
            if (EPI == 0) {
                C[idx] = v;
            } else if (EPI == 1) {
                if (col < 128) {
                    float t = v + aux0[col];
                    C[(size_t)row*128 + col] = (t > 20.f) ? t : log1pf(__expf(t));
                } else if (col < 144) {
                    o1[(size_t)row*16 + (col - 128)] = v;
                } else {
                    o2[(size_t)row*16 + (col - 144)] = v;
                }
            } else if (EPI == 2) {
                float t = v + aux0[col];
                C[idx] = t > 0.f ? t : 0.f;
            } else if (EPI == 3) {
                C[idx] = v + aux0[idx];
            } else if (EPI == 4) {
                C[idx] = v + aux0[idx] + aux1[col];
            } else if (EPI == 5) {
                C[idx] = 2.f*v - (row == col ? 1.f : 0.f);
            } else if (EPI == 6) {
                C[idx] = v + aux0[col];
            }
        }
    }
}

// ---------------- causal conv (both directions) + silu ----------------
__global__ void conv_silu_k(const float* __restrict__ xz,
                            const float* __restrict__ cw0, const float* __restrict__ cb0,
                            const float* __restrict__ cw1, const float* __restrict__ cb1,
                            float* __restrict__ xc0, float* __restrict__ xc1)
{
    int dir = blockIdx.y;
    int g = blockIdx.x * 256 + threadIdx.x;   // < 16384*128
    int d = g & 127; int m = g >> 7; int l = m & 1023;
    const float* cw = dir ? cw1 : cw0;
    const float* cb = dir ? cb1 : cb0;
    const float* src = xz + dir * 256 + d;
    float acc = cb[d];
    #pragma unroll
    for (int k = 0; k < 4; k++) {
        int ll = dir ? (l + 3 - k) : (l - 3 + k);
        if (ll >= 0 && ll < 1024)
            acc = fmaf(src[(size_t)(m - l + ll) * 512], cw[d*4 + k], acc);
    }
    (dir ? xc1 : xc0)[g] = silu_(acc);
}

// ---------------- chunked selective scan -------------------------------------------
// Pass 1: per chunk local scan from h=0; record H_c (local final state) and
//         E_c = exp(Ads * sum dt) (chunk decay).
__global__ void __launch_bounds__(512) scan_p1(
    const float* __restrict__ dt0, const float* __restrict__ dt1,
    const float* __restrict__ xc0, const float* __restrict__ xc1,
    const float* __restrict__ B0,  const float* __restrict__ B1,
    const float* __restrict__ A0,  const float* __restrict__ A1,
    float* __restrict__ Hc, float* __restrict__ Ec)
{
    int dir = blockIdx.z >> 4;
    int b   = blockIdx.z & 15;
    int c   = blockIdx.y;
    int t = threadIdx.x, s = t & 15, dl = t >> 4;
    int d = blockIdx.x * 32 + dl;
    const float* dt = dir ? dt1 : dt0;
    const float* xc = dir ? xc1 : xc0;
    const float* Bm = dir ? B1 : B0;
    float Ads = (dir ? A1 : A0)[d*16 + s];
    int l0  = dir ? (1023 - c*CHLEN) : c*CHLEN;
    int stp = dir ? -1 : 1;
    const float* pdt = dt + (size_t)b*131072 + (size_t)l0*128 + d;
    const float* pxc = xc + (size_t)b*131072 + (size_t)l0*128 + d;
    const float* pB  = Bm + (size_t)b*16384  + (size_t)l0*16  + s;
    int d128 = stp*128, d16 = stp*16;
    float h = 0.f, sdt = 0.f;
    float dtv = *pdt, xcv = *pxc, Bv = *pB;
    for (int tt = 0; tt < CHLEN; tt++) {
        float dtv2, xcv2, Bv2;
        if (tt < CHLEN-1) { dtv2 = pdt[d128]; xcv2 = pxc[d128]; Bv2 = pB[d16]; }
        else { dtv2 = xcv2 = Bv2 = 0.f; }
        float e = __expf(dtv * Ads);
        h = fmaf(h, e, dtv * Bv * xcv);
        sdt += dtv;
        pdt += d128; pxc += d128; pB += d16;
        dtv = dtv2; xcv = xcv2; Bv = Bv2;
    }
    size_t idx = ((((size_t)dir*16 + b)*NCHUNK + c)*128 + d)*16 + s;
    Hc[idx] = h;
    Ec[idx] = __expf(Ads * sdt);
}

// Pass 1.5: chain chunk states sequentially (8 steps per lane)
__global__ void scan_comb(const float* __restrict__ Hc, const float* __restrict__ Ec,
                          float* __restrict__ h0arr)
{
    int g = blockIdx.x * 256 + threadIdx.x;   // 65536 = 2*16*128*16
    int s = g & 15; int d = (g >> 4) & 127; int bb = g >> 11;  // bb = dir*16+b
    float carry = 0.f;
    #pragma unroll
    for (int c = 0; c < NCHUNK; c++) {
        size_t idx = (((size_t)bb*NCHUNK + c)*128 + d)*16 + s;
        h0arr[idx] = carry;
        carry = fmaf(carry, Ec[idx], Hc[idx]);
    }
}

// Pass 2: replay each chunk from its correct initial state; emit y into ycat
__global__ void __launch_bounds__(512) scan_p2(
    const float* __restrict__ dt0, const float* __restrict__ dt1,
    const float* __restrict__ xc0, const float* __restrict__ xc1,
    const float* __restrict__ B0,  const float* __restrict__ B1,
    const float* __restrict__ C0,  const float* __restrict__ C1,
    const float* __restrict__ xz,
    const float* __restrict__ A0,  const float* __restrict__ A1,
    const float* __restrict__ D0,  const float* __restrict__ D1,
    const float* __restrict__ h0arr, float* __restrict__ ycat)
{
    int dir = blockIdx.z >> 4;
    int b   = blockIdx.z & 15;
    int c   = blockIdx.y;
    int t = threadIdx.x, s = t & 15, dl = t >> 4;
    int d = blockIdx.x * 32 + dl;
    const float* dt = dir ? dt1 : dt0;
    const float* xc = dir ? xc1 : xc0;
    const float* Bm = dir ? B1 : B0;
    const float* Cm = dir ? C1 : C0;
    float Ads = (dir ? A1 : A0)[d*16 + s];
    float Dpd = (dir ? D1 : D0)[d];
    int l0  = dir ? (1023 - c*CHLEN) : c*CHLEN;
    int stp = dir ? -1 : 1;
    const float* pdt = dt + (size_t)b*131072 + (size_t)l0*128 + d;
    const float* pxc = xc + (size_t)b*131072 + (size_t)l0*128 + d;
    const float* pB  = Bm + (size_t)b*16384  + (size_t)l0*16  + s;
    const float* pC  = Cm + (size_t)b*16384  + (size_t)l0*16  + s;
    const float* pz  = xz + (size_t)b*524288 + (size_t)l0*512 + dir*256 + 128 + d;
    float* py        = ycat + (size_t)b*262144 + (size_t)l0*256 + dir*128 + d;
    int d128 = stp*128, d16 = stp*16, d512 = stp*512, d256 = stp*256;

    size_t idx = ((((size_t)dir*16 + b)*NCHUNK + c)*128 + d)*16 + s;
    float h = h0arr[idx];

    float dtv = *pdt, xcv = *pxc, Bv = *pB, Cv = *pC, zv = *pz;
    for (int tt = 0; tt < CHLEN; tt++) {
        float dtv2, xcv2, Bv2, Cv2, zv2;
        if (tt < CHLEN-1) {
            dtv2 = pdt[d128]; xcv2 = pxc[d128];
            Bv2  = pB[d16];   Cv2  = pC[d16];
            zv2  = pz[d512];
        } else { dtv2 = xcv2 = Bv2 = Cv2 = zv2 = 0.f; }
        float e = __expf(dtv * Ads);
        h = fmaf(h, e, dtv * Bv * xcv);
        float part = h * Cv;
        part += __shfl_xor_sync(0xffffffffu, part, 8);
        part += __shfl_xor_sync(0xffffffffu, part, 4);
        part += __shfl_xor_sync(0xffffffffu, part, 2);
        part += __shfl_xor_sync(0xffffffffu, part, 1);
        if (s == 0)
            py[0] = (part + Dpd * xcv) * silu_(zv);
        pdt += d128; pxc += d128; pB += d16; pC += d16; pz += d512; py += d256;
        dtv = dtv2; xcv = xcv2; Bv = Bv2; Cv = Cv2; zv = zv2;
    }
}

// ---------------- support matrix: softmax(relu(E E^T)) ----------------
__global__ void __launch_bounds__(256) sup_k(const float* __restrict__ emb, float* __restrict__ sup)
{
    __shared__ float se[NNODE * EDIM];
    __shared__ float red[256];
    int n = blockIdx.x, tid = threadIdx.x;
    for (int i = tid; i < NNODE*EDIM; i += 256) se[i] = emb[i];
    __syncthreads();
    float en[EDIM];
    #pragma unroll
    for (int e = 0; e < EDIM; e++) en[e] = se[n*EDIM + e];
    float vals[4]; float mx = -1e30f;
    #pragma unroll
    for (int jj = 0; jj < 4; jj++) {
        int j = jj*256 + tid;
        float v = 0.f;
        #pragma unroll
        for (int e = 0; e < EDIM; e++) v = fmaf(en[e], se[j*EDIM + e], v);
        v = v > 0.f ? v : 0.f;
        vals[jj] = v; mx = fmaxf(mx, v);
    }
    red[tid] = mx; __syncthreads();
    for (int o = 128; o > 0; o >>= 1) { if (tid < o) red[tid] = fmaxf(red[tid], red[tid+o]); __syncthreads(); }
    mx = red[0]; __syncthreads();
    float s = 0.f;
    #pragma unroll
    for (int jj = 0; jj < 4; jj++) { vals[jj] = __expf(vals[jj] - mx); s += vals[jj]; }
    red[tid] = s; __syncthreads();
    for (int o = 128; o > 0; o >>= 1) { if (tid < o) red[tid] += red[tid+o]; __syncthreads(); }
    float inv = 1.f / red[0];
    #pragma unroll
    for (int jj = 0; jj < 4; jj++) sup[(size_t)n*1024 + jj*256 + tid] = vals[jj] * inv;
}

// ---------------- W[n,k,c,o] = sum_e emb[n,e] W_pool[e,k,c,o] ----------------
__global__ void wmix_k(const float* __restrict__ emb, const float* __restrict__ wp,
                       float* __restrict__ W)
{
    int n = blockIdx.y;
    int j = blockIdx.x * 256 + threadIdx.x;  // < 12288
    float acc = 0.f;
    #pragma unroll
    for (int e = 0; e < EDIM; e++) acc = fmaf(emb[n*EDIM + e], wp[(size_t)e*12288 + j], acc);
    W[(size_t)n*12288 + j] = acc;
}

// ---------------- per-node graph conv ----------------
__global__ void __launch_bounds__(256) gconv_k(
    const float* __restrict__ x,  const float* __restrict__ xg1,
    const float* __restrict__ xg2, const float* __restrict__ W,
    const float* __restrict__ emb, const float* __restrict__ bp,
    float* __restrict__ go)
{
    __shared__ float xs[3072];
    __shared__ float bs[64];
    int n = blockIdx.x, tid = threadIdx.x;
    const float* Wn = W + (size_t)n * 12288;
    for (int i = tid; i < 3072; i += 256) {
        int k = i >> 10; int rem = i & 1023; int b = rem >> 6; int c = rem & 63;
        const float* src = (k == 0) ? x : (k == 1 ? xg1 : xg2);
        xs[i] = src[(size_t)b*65536 + (size_t)n*64 + c];
    }
    if (tid < 64) {
        float a = 0.f;
        #pragma unroll
        for (int e = 0; e < EDIM; e++) a = fmaf(emb[n*EDIM + e], bp[e*64 + tid], a);
        bs[tid] = a;
    }
    __syncthreads();
    int o = tid & 63, bq = tid >> 6;
    float acc[4];
    #pragma unroll
    for (int q = 0; q < 4; q++) acc[q] = bs[o];
    #pragma unroll 4
    for (int kc = 0; kc < 192; kc++) {
        float w = __ldg(Wn + kc*64 + o);
        int k = kc >> 6, c = kc & 63;
        #pragma unroll
        for (int q = 0; q < 4; q++)
            acc[q] = fmaf(xs[(k*16 + bq + q*4)*64 + c], w, acc[q]);
    }
    #pragma unroll
    for (int q = 0; q < 4; q++) {
        int b = bq + q*4;
        go[(size_t)b*65536 + (size_t)n*64 + o] = acc[q];
    }
}

// ---------------- launch ----------------
extern "C" void kernel_launch(void* const* d_in, const int* in_sizes, int n_in,
                              void* d_out, int out_size)
{
    const float* x_in     = (const float*)d_in[0];
    const float* fw_in    = (const float*)d_in[1];
    const float* fw_cw    = (const float*)d_in[2];
    const float* fw_cb    = (const float*)d_in[3];
    const float* fw_xp    = (const float*)d_in[4];
    const float* fw_dtw   = (const float*)d_in[5];
    const float* fw_dtb   = (const float*)d_in[6];
    const float* fw_Alog  = (const float*)d_in[7];
    const float* fw_D     = (const float*)d_in[8];
    const float* fw_out   = (const float*)d_in[9];
    const float* bw_in    = (const float*)d_in[10];
    const float* bw_cw    = (const float*)d_in[11];
    const float* bw_cb    = (const float*)d_in[12];
    const float* bw_xp    = (const float*)d_in[13];
    const float* bw_dtw   = (const float*)d_in[14];
    const float* bw_dtb   = (const float*)d_in[15];
    const float* bw_Alog  = (const float*)d_in[16];
    const float* bw_D     = (const float*)d_in[17];
    const float* bw_out   = (const float*)d_in[18];
    const float* ln1_g    = (const float*)d_in[19];
    const float* ln1_b    = (const float*)d_in[20];
    const float* ffn_w1   = (const float*)d_in[21];
    const float* ffn_b1   = (const float*)d_in[22];
    const float* ffn_w2   = (const float*)d_in[23];
    const float* ffn_b2   = (const float*)d_in[24];
    const float* ln2_g    = (const float*)d_in[25];
    const float* ln2_b    = (const float*)d_in[26];
    const float* node_emb = (const float*)d_in[27];
    const float* W_pool   = (const float*)d_in[28];
    const float* b_pool   = (const float*)d_in[29];
    const float* proj_w   = (const float*)d_in[30];
    const float* proj_b   = (const float*)d_in[31];
    float* outp = (float*)d_out;

    float* S = nullptr;
    cudaGetSymbolAddress((void**)&S, g_scratch);

    float* Wcat   = S;
    float* Wcomb0 = S + 32768;
    float* Wcomb1 = S + 53248;
    float* A0     = S + 73728;
    float* A1     = S + 75776;
    float* xz     = S + 77824;
    float* xc0    = S + 8466432;
    float* xc1    = S + 10563584;
    float* dt0    = S + 12660736;
    float* dt1    = S + 14757888;
    float* Bm0    = S + 16855040;
    float* Bm1    = S + 17117184;
    float* Cm0    = S + 17379328;
    float* Cm1    = S + 17641472;
    float* ycat   = S + 17903616;   // (M,256)
    float* xbuf   = S + 22097920;
    float* xln    = S + 23146496;
    float* hbuf   = S + 25243648;
    float* sup    = S + 29437952;
    float* cheb   = S + 30486528;
    float* xg1    = S + 31535104;
    float* xg2    = S + 32583680;
    float* Wbig   = S + 33632256;
    float* go     = S + 46215168;
    float* Wocat  = S + 47263744;   // (256,64)
    float* Hc     = S + 47280128;   // 524288
    float* Ec     = S + 47804416;   // 524288
    float* h0arr  = S + 48328704;   // 524288

    // prep: weights + x copy
    {
        int total = 32768 + 40960 + 4096 + 16384 + MROWS*DMODEL;
        prep_k<<<(total + 255)/256, 256>>>(fw_in, bw_in, fw_xp, fw_dtw, bw_xp, bw_dtw,
                                           fw_Alog, bw_Alog, fw_out, bw_out, x_in,
                                           Wcat, Wcomb0, Wcomb1, A0, A1, Wocat, xbuf);
    }

    for (int layer = 0; layer < 2; layer++) {
        // xz = x @ [fw_in | bw_in]   (16384 x 512)
        sgemm_k<0><<<dim3(8, 256, 1), 256>>>(xbuf, Wcat, xz, MROWS, 512, 64,
                                             0, 0, 0, nullptr, nullptr, nullptr, nullptr);
        // conv + silu, both dirs
        conv_silu_k<<<dim3((MROWS*128)/256, 2, 1), 256>>>(xz, fw_cw, fw_cb, bw_cw, bw_cb, xc0, xc1);
        // xproj -> dt (softplus), Bm, Cm
        sgemm_k<1><<<dim3(3, 256, 1), 256>>>(xc0, Wcomb0, dt0, MROWS, 160, 128,
                                             0, 0, 0, fw_dtb, nullptr, Bm0, Cm0);
        sgemm_k<1><<<dim3(3, 256, 1), 256>>>(xc1, Wcomb1, dt1, MROWS, 160, 128,
                                             0, 0, 0, bw_dtb, nullptr, Bm1, Cm1);
        // chunked selective scan, both dirs
        scan_p1<<<dim3(4, NCHUNK, 32), 512>>>(dt0, dt1, xc0, xc1, Bm0, Bm1, A0, A1, Hc, Ec);
        scan_comb<<<256, 256>>>(Hc, Ec, h0arr);
        scan_p2<<<dim3(4, NCHUNK, 32), 512>>>(dt0, dt1, xc0, xc1, Bm0, Bm1, Cm0, Cm1,
                                              xz, A0, A1, fw_D, bw_D, h0arr, ycat);
        // x + [yf|yb] @ Wocat, fused LayerNorm-1 -> xln
        sgemm_k<7><<<dim3(1, 256, 1), 256>>>(ycat, Wocat, xln, MROWS, 64, 256,
                                             0, 0, 0, xbuf, nullptr,
                                             (float*)ln1_g, (float*)ln1_b);
        // FFN
        sgemm_k<2><<<dim3(4, 256, 1), 256>>>(xln, ffn_w1, hbuf, MROWS, 256, 64,
                                             0, 0, 0, ffn_b1, nullptr, nullptr, nullptr);
        // xln + relu(...)@W2 + b2, fused LayerNorm-2 -> xbuf (next layer input)
        sgemm_k<8><<<dim3(1, 256, 1), 256>>>(hbuf, ffn_w2, xbuf, MROWS, 64, 256,
                                             0, 0, 0, xln, ffn_b2,
                                             (float*)ln2_g, (float*)ln2_b);
    }

    // graph part
    sup_k<<<NNODE, 256>>>(node_emb, sup);
    // cheb2 = 2*sup@sup - I
    sgemm_k<5><<<dim3(16, 16, 1), 256>>>(sup, sup, cheb, 1024, 1024, 1024,
                                         0, 0, 0, nullptr, nullptr, nullptr, nullptr);
    // xg1[b] = sup @ x_b ; xg2[b] = cheb2 @ x_b  (batched over b)
    sgemm_k<0><<<dim3(1, 16, 16), 256>>>(sup, xbuf, xg1, 1024, 64, 1024,
                                         0, 65536, 65536, nullptr, nullptr, nullptr, nullptr);
    sgemm_k<0><<<dim3(1, 16, 16), 256>>>(cheb, xbuf, xg2, 1024, 64, 1024,
                                         0, 65536, 65536, nullptr, nullptr, nullptr, nullptr);
    // mixed weights
    wmix_k<<<dim3(48, 1024, 1), 256>>>(node_emb, W_pool, Wbig);
    // per-node contraction
    gconv_k<<<NNODE, 256>>>(xbuf, xg1, xg2, Wbig, node_emb, b_pool, go);
    // final projection + bias -> d_out
    sgemm_k<6><<<dim3(2, 256, 1), 256>>>(go, proj_w, outp, MROWS, PLOUT, 64,
                                         0, 0, 0, proj_b, nullptr, nullptr, nullptr);
}